// round 1
// baseline (speedup 1.0000x reference)
#include <cuda_runtime.h>

#define NPTS 8192
#define D 64
#define SCALE 0.125f   // 1/sqrt(64)

// ---------------- scratch (device globals; no allocations allowed) ----------
__device__ float g_q[2][NPTS * D];
__device__ float g_k[2][NPTS * D];
__device__ float g_att[2][NPTS * D];
__device__ float g_nrm[2][NPTS];

// XOR swizzle at float4 granularity for [64][64] fp32 tiles stored k-major.
// chunk index for (k, row-chunk c4): conflict-free vectorized loads.
__device__ __forceinline__ int sw64(int k, int c4) { return k * 16 + (c4 ^ (k & 15)); }
// same for [64][128] tiles (32 chunks per k-row)
__device__ __forceinline__ int sw128(int k, int c4) { return k * 32 + (c4 ^ (k & 31)); }

// ---------------- 1) projections: Q = X@Wq, K = X@Wk for both inputs -------
__global__ void proj_kernel(const float* __restrict__ x, const float* __restrict__ y,
                            const float* __restrict__ Wq, const float* __restrict__ Wk)
{
    __shared__ float wq[D * D], wk[D * D];
    __shared__ float xs[4][D];
    int tx = threadIdx.x;           // 0..63  (output column)
    int ty = threadIdx.y;           // 0..3   (row within block)
    int tid = ty * D + tx;
    for (int i = tid; i < D * D; i += 256) { wq[i] = Wq[i]; wk[i] = Wk[i]; }

    int w = blockIdx.y;
    const float* in = w ? y : x;
    int row = blockIdx.x * 4 + ty;
    xs[ty][tx] = in[row * D + tx];
    __syncthreads();

    float aq = 0.f, ak = 0.f;
#pragma unroll
    for (int k = 0; k < D; k++) {
        float v = xs[ty][k];
        aq = fmaf(v, wq[k * D + tx], aq);
        ak = fmaf(v, wk[k * D + tx], ak);
    }
    g_q[w][row * D + tx] = aq;
    g_k[w][row * D + tx] = ak;
}

// ---------------- 2) flash attention (BM = BN = 64, 256 threads) -----------
// thread (tx = tid&15, ty = tid>>4): owns S rows ty*4..+3, cols tx*4..+3,
// and O rows ty*4..+3, dims tx*4..+3. Shuffle reductions over the tx group.
__global__ __launch_bounds__(256, 2)
void attn_kernel(const float* __restrict__ x, const float* __restrict__ y)
{
    extern __shared__ float4 sm[];
    float4* Qs = sm;          // [64][16] chunks, swizzled, k-major
    float4* Ks = sm + 1024;   // same
    float4* Vs = sm + 2048;   // [j][16] chunks, swizzled (row-major over d)
    float4* Ps = sm + 3072;   // [j][16] chunks over rows, swizzled

    int tid = threadIdx.x;
    int tx = tid & 15, ty = tid >> 4;
    int w = blockIdx.y;
    const float* Vg = w ? y : x;
    const float* Qg = g_q[w];
    const float* Kg = g_k[w];
    int rowblk = blockIdx.x * 64;

    // load Q tile: transpose to k-major with swizzle
    for (int e = tid; e < 4096; e += 256) {
        int r = e >> 6, c = e & 63;
        ((float*)Qs)[sw64(c, r >> 2) * 4 + (r & 3)] = Qg[(rowblk + r) * D + c];
    }

    float o[4][4], m[4], l[4];
#pragma unroll
    for (int rr = 0; rr < 4; rr++) {
        m[rr] = -1e30f; l[rr] = 0.f;
#pragma unroll
        for (int cc = 0; cc < 4; cc++) o[rr][cc] = 0.f;
    }

    for (int t = 0; t < NPTS / 64; t++) {
        int kb = t * 64;
        __syncthreads();   // protects Ks/Vs/Ps reuse from previous iteration
        for (int e = tid; e < 4096; e += 256) {
            int r = e >> 6, c = e & 63;
            ((float*)Ks)[sw64(c, r >> 2) * 4 + (r & 3)] = Kg[kb * D + e];
        }
        const float4* Vg4 = (const float4*)(Vg + kb * D);
        for (int e4 = tid; e4 < 1024; e4 += 256) {
            int j = e4 >> 4, d4 = e4 & 15;
            Vs[sw64(j, d4)] = Vg4[e4];
        }
        __syncthreads();

        // S = Q @ K^T  (raw scores; scale applied inside exp)
        float s[4][4];
#pragma unroll
        for (int rr = 0; rr < 4; rr++)
#pragma unroll
            for (int cc = 0; cc < 4; cc++) s[rr][cc] = 0.f;

#pragma unroll 16
        for (int k = 0; k < 64; k++) {
            float4 a = Qs[sw64(k, ty)];
            float4 b = Ks[sw64(k, tx)];
            float av[4] = {a.x, a.y, a.z, a.w};
            float bv[4] = {b.x, b.y, b.z, b.w};
#pragma unroll
            for (int rr = 0; rr < 4; rr++)
#pragma unroll
                for (int cc = 0; cc < 4; cc++)
                    s[rr][cc] = fmaf(av[rr], bv[cc], s[rr][cc]);
        }

        // online softmax (per row; stats replicated across the 16 tx lanes)
#pragma unroll
        for (int rr = 0; rr < 4; rr++) {
            float mt = fmaxf(fmaxf(s[rr][0], s[rr][1]), fmaxf(s[rr][2], s[rr][3]));
#pragma unroll
            for (int msk = 8; msk; msk >>= 1)
                mt = fmaxf(mt, __shfl_xor_sync(0xffffffffu, mt, msk));
            float mn = fmaxf(m[rr], mt);
            float corr = __expf((m[rr] - mn) * SCALE);
            float rs = 0.f;
#pragma unroll
            for (int cc = 0; cc < 4; cc++) {
                s[rr][cc] = __expf((s[rr][cc] - mn) * SCALE);
                rs += s[rr][cc];
            }
#pragma unroll
            for (int msk = 8; msk; msk >>= 1)
                rs += __shfl_xor_sync(0xffffffffu, rs, msk);
            l[rr] = l[rr] * corr + rs;
            m[rr] = mn;
#pragma unroll
            for (int cc = 0; cc < 4; cc++) o[rr][cc] *= corr;
        }

        // stage P into smem (vectorized over the 4 owned rows)
#pragma unroll
        for (int cc = 0; cc < 4; cc++)
            Ps[sw64(tx * 4 + cc, ty)] =
                make_float4(s[0][cc], s[1][cc], s[2][cc], s[3][cc]);
        __syncthreads();

        // O += P @ V
#pragma unroll 16
        for (int j = 0; j < 64; j++) {
            float4 a = Ps[sw64(j, ty)];
            float4 b = Vs[sw64(j, tx)];
            float av[4] = {a.x, a.y, a.z, a.w};
            float bv[4] = {b.x, b.y, b.z, b.w};
#pragma unroll
            for (int rr = 0; rr < 4; rr++)
#pragma unroll
                for (int cc = 0; cc < 4; cc++)
                    o[rr][cc] = fmaf(av[rr], bv[cc], o[rr][cc]);
        }
    }

    // epilogue: normalize, store att, store row norms
    float* Ag = g_att[w];
#pragma unroll
    for (int rr = 0; rr < 4; rr++) {
        int row = rowblk + ty * 4 + rr;
        float inv = 1.f / l[rr];
        float4 v = make_float4(o[rr][0] * inv, o[rr][1] * inv,
                               o[rr][2] * inv, o[rr][3] * inv);
        *(float4*)(Ag + row * D + tx * 4) = v;
        float n = v.x * v.x + v.y * v.y + v.z * v.z + v.w * v.w;
#pragma unroll
        for (int msk = 8; msk; msk >>= 1)
            n += __shfl_xor_sync(0xffffffffu, n, msk);
        if (tx == 0) g_nrm[w][row] = n;
    }
}

// ---------------- 3) pairwise RBF: out[i][j] = exp(2*dot - nx - ny) --------
// 128x128 output tile per CTA, 256 threads, 8x8 microtile (split 4+4).
__global__ __launch_bounds__(256, 2)
void pair_kernel(float* __restrict__ out)
{
    extern __shared__ float4 sm[];
    float4* XA = sm;          // [k=64][32] chunks, swizzled
    float4* YA = sm + 2048;

    int tid = threadIdx.x;
    int tx = tid & 15, ty = tid >> 4;
    int i0 = blockIdx.x * 128, j0 = blockIdx.y * 128;
    const float* xa = g_att[0];
    const float* ya = g_att[1];

    for (int e = tid; e < 8192; e += 256) {
        int r = e >> 6, c = e & 63;
        ((float*)XA)[sw128(c, r >> 2) * 4 + (r & 3)] = xa[(i0 + r) * D + c];
        ((float*)YA)[sw128(c, r >> 2) * 4 + (r & 3)] = ya[(j0 + r) * D + c];
    }

    float acc[8][8];
#pragma unroll
    for (int rr = 0; rr < 8; rr++)
#pragma unroll
        for (int cc = 0; cc < 8; cc++) acc[rr][cc] = 0.f;
    __syncthreads();

#pragma unroll 8
    for (int k = 0; k < 64; k++) {
        float4 a0 = XA[sw128(k, ty)];
        float4 a1 = XA[sw128(k, 16 + ty)];
        float4 b0 = YA[sw128(k, tx)];
        float4 b1 = YA[sw128(k, 16 + tx)];
        float av[8] = {a0.x, a0.y, a0.z, a0.w, a1.x, a1.y, a1.z, a1.w};
        float bv[8] = {b0.x, b0.y, b0.z, b0.w, b1.x, b1.y, b1.z, b1.w};
#pragma unroll
        for (int rr = 0; rr < 8; rr++)
#pragma unroll
            for (int cc = 0; cc < 8; cc++)
                acc[rr][cc] = fmaf(av[rr], bv[cc], acc[rr][cc]);
    }

    int ri[8], cj[8];
    float nx[8], ny[8];
#pragma unroll
    for (int q = 0; q < 8; q++) {
        ri[q] = i0 + ((q < 4) ? (ty * 4 + q) : (64 + ty * 4 + q - 4));
        cj[q] = j0 + ((q < 4) ? (tx * 4 + q) : (64 + tx * 4 + q - 4));
        nx[q] = g_nrm[0][ri[q]];
        ny[q] = g_nrm[1][cj[q]];
    }

#pragma unroll
    for (int rr = 0; rr < 8; rr++) {
        float4 v0 = make_float4(__expf(2.f * acc[rr][0] - nx[rr] - ny[0]),
                                __expf(2.f * acc[rr][1] - nx[rr] - ny[1]),
                                __expf(2.f * acc[rr][2] - nx[rr] - ny[2]),
                                __expf(2.f * acc[rr][3] - nx[rr] - ny[3]));
        float4 v1 = make_float4(__expf(2.f * acc[rr][4] - nx[rr] - ny[4]),
                                __expf(2.f * acc[rr][5] - nx[rr] - ny[5]),
                                __expf(2.f * acc[rr][6] - nx[rr] - ny[6]),
                                __expf(2.f * acc[rr][7] - nx[rr] - ny[7]));
        float* rowp = out + (size_t)ri[rr] * NPTS;
        *(float4*)(rowp + j0 + tx * 4) = v0;
        *(float4*)(rowp + j0 + 64 + tx * 4) = v1;
    }
}

// ---------------- launcher -------------------------------------------------
extern "C" void kernel_launch(void* const* d_in, const int* in_sizes, int n_in,
                              void* d_out, int out_size)
{
    const float* Wq = (const float*)d_in[0];   // rotation_params
    const float* Wk = (const float*)d_in[1];   // entangle_params
    const float* x  = (const float*)d_in[2];
    const float* y  = (const float*)d_in[3];
    float* out = (float*)d_out;

    // 64 KB dynamic smem per CTA (idempotent; legal outside stream capture scope)
    cudaFuncSetAttribute(attn_kernel, cudaFuncAttributeMaxDynamicSharedMemorySize, 64 * 1024);
    cudaFuncSetAttribute(pair_kernel, cudaFuncAttributeMaxDynamicSharedMemorySize, 64 * 1024);

    proj_kernel<<<dim3(NPTS / 4, 2), dim3(64, 4)>>>(x, y, Wq, Wk);
    attn_kernel<<<dim3(NPTS / 64, 2), 256, 64 * 1024>>>(x, y);
    pair_kernel<<<dim3(NPTS / 128, NPTS / 128), 256, 64 * 1024>>>(out);
}

// round 2
// speedup vs baseline: 1.0002x; 1.0002x over previous
#include <cuda_runtime.h>

#define NPTS 8192
#define D 64
#define SCALE 0.125f   // 1/sqrt(64)

// ---------------- scratch (device globals; no allocations allowed) ----------
__device__ float g_q[2][NPTS * D];
__device__ float g_k[2][NPTS * D];
__device__ float g_att[2][NPTS * D];
__device__ float g_nrm[2][NPTS];

// XOR swizzle at float4 granularity for [64][64] fp32 tiles stored k-major.
// chunk index for (k, row-chunk c4): conflict-free vectorized loads.
__device__ __forceinline__ int sw64(int k, int c4) { return k * 16 + (c4 ^ (k & 15)); }
// same for [64][128] tiles (32 chunks per k-row)
__device__ __forceinline__ int sw128(int k, int c4) { return k * 32 + (c4 ^ (k & 31)); }

// ---------------- 1) projections: Q = X@Wq, K = X@Wk for both inputs -------
__global__ void proj_kernel(const float* __restrict__ x, const float* __restrict__ y,
                            const float* __restrict__ Wq, const float* __restrict__ Wk)
{
    __shared__ float wq[D * D], wk[D * D];
    __shared__ float xs[4][D];
    int tx = threadIdx.x;           // 0..63  (output column)
    int ty = threadIdx.y;           // 0..3   (row within block)
    int tid = ty * D + tx;
    for (int i = tid; i < D * D; i += 256) { wq[i] = Wq[i]; wk[i] = Wk[i]; }

    int w = blockIdx.y;
    const float* in = w ? y : x;
    int row = blockIdx.x * 4 + ty;
    xs[ty][tx] = in[row * D + tx];
    __syncthreads();

    float aq = 0.f, ak = 0.f;
#pragma unroll
    for (int k = 0; k < D; k++) {
        float v = xs[ty][k];
        aq = fmaf(v, wq[k * D + tx], aq);
        ak = fmaf(v, wk[k * D + tx], ak);
    }
    g_q[w][row * D + tx] = aq;
    g_k[w][row * D + tx] = ak;
}

// ---------------- 2) flash attention (BM = BN = 64, 256 threads) -----------
// thread (tx = tid&15, ty = tid>>4): owns S rows ty*4..+3, cols tx*4..+3,
// and O rows ty*4..+3, dims tx*4..+3. Shuffle reductions over the tx group.
__global__ __launch_bounds__(256, 2)
void attn_kernel(const float* __restrict__ x, const float* __restrict__ y)
{
    extern __shared__ float4 sm[];
    float4* Qs = sm;          // [64][16] chunks, swizzled, k-major
    float4* Ks = sm + 1024;   // same
    float4* Vs = sm + 2048;   // [j][16] chunks, swizzled (row-major over d)
    float4* Ps = sm + 3072;   // [j][16] chunks over rows, swizzled

    int tid = threadIdx.x;
    int tx = tid & 15, ty = tid >> 4;
    int w = blockIdx.y;
    const float* Vg = w ? y : x;
    const float* Qg = g_q[w];
    const float* Kg = g_k[w];
    int rowblk = blockIdx.x * 64;

    // load Q tile: transpose to k-major with swizzle
    for (int e = tid; e < 4096; e += 256) {
        int r = e >> 6, c = e & 63;
        ((float*)Qs)[sw64(c, r >> 2) * 4 + (r & 3)] = Qg[(rowblk + r) * D + c];
    }

    float o[4][4], m[4], l[4];
#pragma unroll
    for (int rr = 0; rr < 4; rr++) {
        m[rr] = -1e30f; l[rr] = 0.f;
#pragma unroll
        for (int cc = 0; cc < 4; cc++) o[rr][cc] = 0.f;
    }

    for (int t = 0; t < NPTS / 64; t++) {
        int kb = t * 64;
        __syncthreads();   // protects Ks/Vs/Ps reuse from previous iteration
        for (int e = tid; e < 4096; e += 256) {
            int r = e >> 6, c = e & 63;
            ((float*)Ks)[sw64(c, r >> 2) * 4 + (r & 3)] = Kg[kb * D + e];
        }
        const float4* Vg4 = (const float4*)(Vg + kb * D);
        for (int e4 = tid; e4 < 1024; e4 += 256) {
            int j = e4 >> 4, d4 = e4 & 15;
            Vs[sw64(j, d4)] = Vg4[e4];
        }
        __syncthreads();

        // S = Q @ K^T  (raw scores; scale applied inside exp)
        float s[4][4];
#pragma unroll
        for (int rr = 0; rr < 4; rr++)
#pragma unroll
            for (int cc = 0; cc < 4; cc++) s[rr][cc] = 0.f;

#pragma unroll 16
        for (int k = 0; k < 64; k++) {
            float4 a = Qs[sw64(k, ty)];
            float4 b = Ks[sw64(k, tx)];
            float av[4] = {a.x, a.y, a.z, a.w};
            float bv[4] = {b.x, b.y, b.z, b.w};
#pragma unroll
            for (int rr = 0; rr < 4; rr++)
#pragma unroll
                for (int cc = 0; cc < 4; cc++)
                    s[rr][cc] = fmaf(av[rr], bv[cc], s[rr][cc]);
        }

        // online softmax (per row; stats replicated across the 16 tx lanes)
#pragma unroll
        for (int rr = 0; rr < 4; rr++) {
            float mt = fmaxf(fmaxf(s[rr][0], s[rr][1]), fmaxf(s[rr][2], s[rr][3]));
#pragma unroll
            for (int msk = 8; msk; msk >>= 1)
                mt = fmaxf(mt, __shfl_xor_sync(0xffffffffu, mt, msk));
            float mn = fmaxf(m[rr], mt);
            float corr = __expf((m[rr] - mn) * SCALE);
            float rs = 0.f;
#pragma unroll
            for (int cc = 0; cc < 4; cc++) {
                s[rr][cc] = __expf((s[rr][cc] - mn) * SCALE);
                rs += s[rr][cc];
            }
#pragma unroll
            for (int msk = 8; msk; msk >>= 1)
                rs += __shfl_xor_sync(0xffffffffu, rs, msk);
            l[rr] = l[rr] * corr + rs;
            m[rr] = mn;
#pragma unroll
            for (int cc = 0; cc < 4; cc++) o[rr][cc] *= corr;
        }

        // stage P into smem (vectorized over the 4 owned rows)
#pragma unroll
        for (int cc = 0; cc < 4; cc++)
            Ps[sw64(tx * 4 + cc, ty)] =
                make_float4(s[0][cc], s[1][cc], s[2][cc], s[3][cc]);
        __syncthreads();

        // O += P @ V
#pragma unroll 16
        for (int j = 0; j < 64; j++) {
            float4 a = Ps[sw64(j, ty)];
            float4 b = Vs[sw64(j, tx)];
            float av[4] = {a.x, a.y, a.z, a.w};
            float bv[4] = {b.x, b.y, b.z, b.w};
#pragma unroll
            for (int rr = 0; rr < 4; rr++)
#pragma unroll
                for (int cc = 0; cc < 4; cc++)
                    o[rr][cc] = fmaf(av[rr], bv[cc], o[rr][cc]);
        }
    }

    // epilogue: normalize, store att, store row norms
    float* Ag = g_att[w];
#pragma unroll
    for (int rr = 0; rr < 4; rr++) {
        int row = rowblk + ty * 4 + rr;
        float inv = 1.f / l[rr];
        float4 v = make_float4(o[rr][0] * inv, o[rr][1] * inv,
                               o[rr][2] * inv, o[rr][3] * inv);
        *(float4*)(Ag + row * D + tx * 4) = v;
        float n = v.x * v.x + v.y * v.y + v.z * v.z + v.w * v.w;
#pragma unroll
        for (int msk = 8; msk; msk >>= 1)
            n += __shfl_xor_sync(0xffffffffu, n, msk);
        if (tx == 0) g_nrm[w][row] = n;
    }
}

// ---------------- 3) pairwise RBF: out[i][j] = exp(2*dot - nx - ny) --------
// 128x128 output tile per CTA, 256 threads, 8x8 microtile (split 4+4).
__global__ __launch_bounds__(256, 2)
void pair_kernel(float* __restrict__ out)
{
    extern __shared__ float4 sm[];
    float4* XA = sm;          // [k=64][32] chunks, swizzled
    float4* YA = sm + 2048;

    int tid = threadIdx.x;
    int tx = tid & 15, ty = tid >> 4;
    int i0 = blockIdx.x * 128, j0 = blockIdx.y * 128;
    const float* xa = g_att[0];
    const float* ya = g_att[1];

    for (int e = tid; e < 8192; e += 256) {
        int r = e >> 6, c = e & 63;
        ((float*)XA)[sw128(c, r >> 2) * 4 + (r & 3)] = xa[(i0 + r) * D + c];
        ((float*)YA)[sw128(c, r >> 2) * 4 + (r & 3)] = ya[(j0 + r) * D + c];
    }

    float acc[8][8];
#pragma unroll
    for (int rr = 0; rr < 8; rr++)
#pragma unroll
        for (int cc = 0; cc < 8; cc++) acc[rr][cc] = 0.f;
    __syncthreads();

#pragma unroll 8
    for (int k = 0; k < 64; k++) {
        float4 a0 = XA[sw128(k, ty)];
        float4 a1 = XA[sw128(k, 16 + ty)];
        float4 b0 = YA[sw128(k, tx)];
        float4 b1 = YA[sw128(k, 16 + tx)];
        float av[8] = {a0.x, a0.y, a0.z, a0.w, a1.x, a1.y, a1.z, a1.w};
        float bv[8] = {b0.x, b0.y, b0.z, b0.w, b1.x, b1.y, b1.z, b1.w};
#pragma unroll
        for (int rr = 0; rr < 8; rr++)
#pragma unroll
            for (int cc = 0; cc < 8; cc++)
                acc[rr][cc] = fmaf(av[rr], bv[cc], acc[rr][cc]);
    }

    int ri[8], cj[8];
    float nx[8], ny[8];
#pragma unroll
    for (int q = 0; q < 8; q++) {
        ri[q] = i0 + ((q < 4) ? (ty * 4 + q) : (64 + ty * 4 + q - 4));
        cj[q] = j0 + ((q < 4) ? (tx * 4 + q) : (64 + tx * 4 + q - 4));
        nx[q] = g_nrm[0][ri[q]];
        ny[q] = g_nrm[1][cj[q]];
    }

#pragma unroll
    for (int rr = 0; rr < 8; rr++) {
        float4 v0 = make_float4(__expf(2.f * acc[rr][0] - nx[rr] - ny[0]),
                                __expf(2.f * acc[rr][1] - nx[rr] - ny[1]),
                                __expf(2.f * acc[rr][2] - nx[rr] - ny[2]),
                                __expf(2.f * acc[rr][3] - nx[rr] - ny[3]));
        float4 v1 = make_float4(__expf(2.f * acc[rr][4] - nx[rr] - ny[4]),
                                __expf(2.f * acc[rr][5] - nx[rr] - ny[5]),
                                __expf(2.f * acc[rr][6] - nx[rr] - ny[6]),
                                __expf(2.f * acc[rr][7] - nx[rr] - ny[7]));
        float* rowp = out + (size_t)ri[rr] * NPTS;
        *(float4*)(rowp + j0 + tx * 4) = v0;
        *(float4*)(rowp + j0 + 64 + tx * 4) = v1;
    }
}

// ---------------- launcher -------------------------------------------------
extern "C" void kernel_launch(void* const* d_in, const int* in_sizes, int n_in,
                              void* d_out, int out_size)
{
    const float* Wq = (const float*)d_in[0];   // rotation_params
    const float* Wk = (const float*)d_in[1];   // entangle_params
    const float* x  = (const float*)d_in[2];
    const float* y  = (const float*)d_in[3];
    float* out = (float*)d_out;

    // 64 KB dynamic smem per CTA (idempotent; legal outside stream capture scope)
    cudaFuncSetAttribute(attn_kernel, cudaFuncAttributeMaxDynamicSharedMemorySize, 64 * 1024);
    cudaFuncSetAttribute(pair_kernel, cudaFuncAttributeMaxDynamicSharedMemorySize, 64 * 1024);

    proj_kernel<<<dim3(NPTS / 4, 2), dim3(64, 4)>>>(x, y, Wq, Wk);
    attn_kernel<<<dim3(NPTS / 64, 2), 256, 64 * 1024>>>(x, y);
    pair_kernel<<<dim3(NPTS / 128, NPTS / 128), 256, 64 * 1024>>>(out);
}